// round 1
// baseline (speedup 1.0000x reference)
#include <cuda_runtime.h>
#include <cstdint>

// Problem constants
#define B_  2
#define L_  2048
#define D_  1024
#define H_  16
#define DK_ 64
#define SCALE_ 0.125f   // 1/sqrt(64)

// Scratch (device globals; no allocation allowed)
__device__ float g_q [B_*H_*L_*DK_];   // [b,h,l,dk]
__device__ float g_kT[B_*H_*DK_*L_];   // [b,h,dk,l]  (K transposed)
__device__ float g_v [B_*H_*L_*DK_];   // [b,h,l,dk]
__device__ float g_o [B_*L_*D_];       // [b,l,h*64+dk]

// ---------------------------------------------------------------------------
// SGEMM 128x128x8, 256 threads, 8x8 per thread.
// A[M,K] row-major, W[K,N] row-major.
// ---------------------------------------------------------------------------

__global__ void __launch_bounds__(256)
sgemm_qkv_kernel(const float* __restrict__ A,
                 const float* __restrict__ W,
                 const float* __restrict__ bias)
{
    const int K = 1024, N = 3072;
    __shared__ float As[8][128];
    __shared__ float Bs[8][128];

    const int tid = threadIdx.x;
    const int m0 = blockIdx.y * 128;
    const int n0 = blockIdx.x * 128;
    const int tx = tid & 15, ty = tid >> 4;

    const int arow = tid >> 1, acol = (tid & 1) * 4;
    const int brow = tid >> 5, bcol = (tid & 31) * 4;

    const float* Aptr = A + (size_t)(m0 + arow) * K + acol;
    const float* Bptr = W + (size_t)brow * N + n0 + bcol;

    float acc[8][8];
#pragma unroll
    for (int i = 0; i < 8; i++)
#pragma unroll
        for (int j = 0; j < 8; j++) acc[i][j] = 0.f;

    for (int k0 = 0; k0 < K; k0 += 8) {
        float4 a4 = *(const float4*)(Aptr + k0);
        float4 b4 = *(const float4*)(Bptr + (size_t)k0 * N);
        __syncthreads();
        As[acol + 0][arow] = a4.x;
        As[acol + 1][arow] = a4.y;
        As[acol + 2][arow] = a4.z;
        As[acol + 3][arow] = a4.w;
        *(float4*)&Bs[brow][bcol] = b4;
        __syncthreads();
#pragma unroll
        for (int kk = 0; kk < 8; kk++) {
            float a[8], b[8];
            *(float4*)&a[0] = *(const float4*)&As[kk][ty * 8];
            *(float4*)&a[4] = *(const float4*)&As[kk][ty * 8 + 4];
            *(float4*)&b[0] = *(const float4*)&Bs[kk][tx * 8];
            *(float4*)&b[4] = *(const float4*)&Bs[kk][tx * 8 + 4];
#pragma unroll
            for (int i = 0; i < 8; i++)
#pragma unroll
                for (int j = 0; j < 8; j++)
                    acc[i][j] += a[i] * b[j];
        }
    }

    // Epilogue: scatter into q / kT / v, add bias.
    const int c_base = n0 + tx * 8;           // global column in [0,3072)
    const int part   = c_base >> 10;          // 0=Q 1=K 2=V (whole tile same part)
    const int r_base = m0 + ty * 8;

    float bv[8];
#pragma unroll
    for (int j = 0; j < 8; j++) bv[j] = bias[c_base + j];

    const int d  = c_base & 1023;
    const int h  = d >> 6;
    const int dk = d & 63;

    if (part == 1) {
        // K: write transposed [b,h,dk,l]
#pragma unroll
        for (int i = 0; i < 8; i++) {
            const int r  = r_base + i;
            const int bI = r >> 11;
            const int l  = r & 2047;
            const size_t hb = (size_t)((bI << 4) + h) * 64;
#pragma unroll
            for (int j = 0; j < 8; j++) {
                g_kT[(hb + (size_t)(dk + j)) * 2048 + l] = acc[i][j] + bv[j];
            }
        }
    } else {
        float* dst = (part == 0) ? g_q : g_v;
#pragma unroll
        for (int i = 0; i < 8; i++) {
            const int r  = r_base + i;
            const int bI = r >> 11;
            const int l  = r & 2047;
            const size_t rb = (((size_t)((bI << 4) + h) * 2048) + l) * 64 + dk;
            float4 v0 = make_float4(acc[i][0] + bv[0], acc[i][1] + bv[1],
                                    acc[i][2] + bv[2], acc[i][3] + bv[3]);
            float4 v1 = make_float4(acc[i][4] + bv[4], acc[i][5] + bv[5],
                                    acc[i][6] + bv[6], acc[i][7] + bv[7]);
            *(float4*)&dst[rb]     = v0;
            *(float4*)&dst[rb + 4] = v1;
        }
    }
}

__global__ void __launch_bounds__(256)
sgemm_out_kernel(const float* __restrict__ W,
                 const float* __restrict__ bias,
                 float* __restrict__ out)
{
    const int K = 1024, N = 1024;
    __shared__ float As[8][128];
    __shared__ float Bs[8][128];

    const int tid = threadIdx.x;
    const int m0 = blockIdx.y * 128;
    const int n0 = blockIdx.x * 128;
    const int tx = tid & 15, ty = tid >> 4;

    const int arow = tid >> 1, acol = (tid & 1) * 4;
    const int brow = tid >> 5, bcol = (tid & 31) * 4;

    const float* Aptr = g_o + (size_t)(m0 + arow) * K + acol;
    const float* Bptr = W + (size_t)brow * N + n0 + bcol;

    float acc[8][8];
#pragma unroll
    for (int i = 0; i < 8; i++)
#pragma unroll
        for (int j = 0; j < 8; j++) acc[i][j] = 0.f;

    for (int k0 = 0; k0 < K; k0 += 8) {
        float4 a4 = *(const float4*)(Aptr + k0);
        float4 b4 = *(const float4*)(Bptr + (size_t)k0 * N);
        __syncthreads();
        As[acol + 0][arow] = a4.x;
        As[acol + 1][arow] = a4.y;
        As[acol + 2][arow] = a4.z;
        As[acol + 3][arow] = a4.w;
        *(float4*)&Bs[brow][bcol] = b4;
        __syncthreads();
#pragma unroll
        for (int kk = 0; kk < 8; kk++) {
            float a[8], b[8];
            *(float4*)&a[0] = *(const float4*)&As[kk][ty * 8];
            *(float4*)&a[4] = *(const float4*)&As[kk][ty * 8 + 4];
            *(float4*)&b[0] = *(const float4*)&Bs[kk][tx * 8];
            *(float4*)&b[4] = *(const float4*)&Bs[kk][tx * 8 + 4];
#pragma unroll
            for (int i = 0; i < 8; i++)
#pragma unroll
                for (int j = 0; j < 8; j++)
                    acc[i][j] += a[i] * b[j];
        }
    }

    const int c_base = n0 + tx * 8;
    const int r_base = m0 + ty * 8;
    float bv[8];
#pragma unroll
    for (int j = 0; j < 8; j++) bv[j] = bias[c_base + j];

#pragma unroll
    for (int i = 0; i < 8; i++) {
        const int r = r_base + i;
        float4 v0 = make_float4(acc[i][0] + bv[0], acc[i][1] + bv[1],
                                acc[i][2] + bv[2], acc[i][3] + bv[3]);
        float4 v1 = make_float4(acc[i][4] + bv[4], acc[i][5] + bv[5],
                                acc[i][6] + bv[6], acc[i][7] + bv[7]);
        *(float4*)&out[(size_t)r * N + c_base]     = v0;
        *(float4*)&out[(size_t)r * N + c_base + 4] = v1;
    }
}

// ---------------------------------------------------------------------------
// Flash attention: 64 queries x 64 keys per tile, 256 threads, 4x4/thread.
// Masked-score semantics: masked score := 0.0 (participates in max & denom),
// masked attn weight := 0 in the PV numerator.
// ---------------------------------------------------------------------------
__global__ void __launch_bounds__(256)
attn_kernel(const int* __restrict__ mask)
{
    __shared__ float Qs[64][64];
    __shared__ float KP[64][64];   // holds K^T tile, then P tile
    __shared__ float Vs[64][64];

    const int tid = threadIdx.x;
    const int tx = tid & 15, ty = tid >> 4;
    const int bh = blockIdx.y;
    const int b  = bh >> 4;
    const int h  = bh & 15;
    const int q0 = blockIdx.x * 64;

    const float* qbase  = g_q  + ((size_t)bh * 2048 + q0) * 64;
    const float* kTbase = g_kT + (size_t)bh * 64 * 2048;
    const float* vbase  = g_v  + (size_t)bh * 2048 * 64;
    const int*   mbase  = mask + ((size_t)b * 2048 + q0) * 2048;

    // Load Q tile
#pragma unroll
    for (int it = 0; it < 4; it++) {
        const int e = it * 256 + tid;
        const int row = e >> 4, c4 = (e & 15) * 4;
        *(float4*)&Qs[row][c4] = *(const float4*)(qbase + (size_t)row * 64 + c4);
    }

    float o[4][4];
#pragma unroll
    for (int i = 0; i < 4; i++)
#pragma unroll
        for (int j = 0; j < 4; j++) o[i][j] = 0.f;
    float m_i[4], l_i[4];
#pragma unroll
    for (int i = 0; i < 4; i++) { m_i[i] = -1e30f; l_i[i] = 0.f; }

    for (int k0 = 0; k0 < 2048; k0 += 64) {
        __syncthreads();   // prior PV reads of KP/Vs done
        // Load K^T tile (KP[dk][key]) and V tile (Vs[key][dk])
#pragma unroll
        for (int it = 0; it < 4; it++) {
            const int e = it * 256 + tid;
            const int row = e >> 4, c4 = (e & 15) * 4;
            *(float4*)&KP[row][c4] = *(const float4*)(kTbase + (size_t)row * 2048 + k0 + c4);
            *(float4*)&Vs[row][c4] = *(const float4*)(vbase + (size_t)(k0 + row) * 64 + c4);
        }
        __syncthreads();

        // S = Q @ K^T  (raw dot products)
        float s[4][4];
#pragma unroll
        for (int i = 0; i < 4; i++)
#pragma unroll
            for (int j = 0; j < 4; j++) s[i][j] = 0.f;

#pragma unroll 8
        for (int kk = 0; kk < 64; kk++) {
            const float4 kv = *(const float4*)&KP[kk][tx * 4];
#pragma unroll
            for (int i = 0; i < 4; i++) {
                const float qv = Qs[ty * 4 + i][kk];
                s[i][0] += qv * kv.x;
                s[i][1] += qv * kv.y;
                s[i][2] += qv * kv.z;
                s[i][3] += qv * kv.w;
            }
        }
        __syncthreads();   // all warps done reading KP as K

        // Mask + online softmax; write P into KP
#pragma unroll
        for (int i = 0; i < 4; i++) {
            const int4 mv = *(const int4*)(mbase + (size_t)(ty * 4 + i) * 2048 + k0 + tx * 4);
            const float sv0 = mv.x ? s[i][0] * SCALE_ : 0.f;
            const float sv1 = mv.y ? s[i][1] * SCALE_ : 0.f;
            const float sv2 = mv.z ? s[i][2] * SCALE_ : 0.f;
            const float sv3 = mv.w ? s[i][3] * SCALE_ : 0.f;

            float rmax = fmaxf(fmaxf(sv0, sv1), fmaxf(sv2, sv3));
#pragma unroll
            for (int off = 8; off; off >>= 1)
                rmax = fmaxf(rmax, __shfl_xor_sync(0xffffffffu, rmax, off));

            const float mn  = fmaxf(m_i[i], rmax);
            const float fac = __expf(m_i[i] - mn);
            const float p0 = __expf(sv0 - mn);
            const float p1 = __expf(sv1 - mn);
            const float p2 = __expf(sv2 - mn);
            const float p3 = __expf(sv3 - mn);

            float rsum = p0 + p1 + p2 + p3;   // denominator includes masked entries
#pragma unroll
            for (int off = 8; off; off >>= 1)
                rsum += __shfl_xor_sync(0xffffffffu, rsum, off);

            l_i[i] = l_i[i] * fac + rsum;
            m_i[i] = mn;
            o[i][0] *= fac; o[i][1] *= fac; o[i][2] *= fac; o[i][3] *= fac;

            float4 pv;
            pv.x = mv.x ? p0 : 0.f;
            pv.y = mv.y ? p1 : 0.f;
            pv.z = mv.z ? p2 : 0.f;
            pv.w = mv.w ? p3 : 0.f;
            *(float4*)&KP[ty * 4 + i][tx * 4] = pv;
        }
        __syncthreads();

        // O += P @ V
#pragma unroll 8
        for (int kk = 0; kk < 64; kk++) {
            const float4 vv = *(const float4*)&Vs[kk][tx * 4];
#pragma unroll
            for (int i = 0; i < 4; i++) {
                const float pp = KP[ty * 4 + i][kk];
                o[i][0] += pp * vv.x;
                o[i][1] += pp * vv.y;
                o[i][2] += pp * vv.z;
                o[i][3] += pp * vv.w;
            }
        }
    }

    // Normalize and store: g_o[b][l][h*64+dk]
#pragma unroll
    for (int i = 0; i < 4; i++) {
        const float inv = 1.0f / l_i[i];
        float4 ov = make_float4(o[i][0] * inv, o[i][1] * inv,
                                o[i][2] * inv, o[i][3] * inv);
        *(float4*)(g_o + ((size_t)b * 2048 + q0 + ty * 4 + i) * 1024 + h * 64 + tx * 4) = ov;
    }
}

// ---------------------------------------------------------------------------

extern "C" void kernel_launch(void* const* d_in, const int* in_sizes, int n_in,
                              void* d_out, int out_size)
{
    const float* x     = (const float*)d_in[0];
    const int*   mask  = (const int*)  d_in[1];
    const float* W_qkv = (const float*)d_in[2];
    const float* b_qkv = (const float*)d_in[3];
    const float* W_out = (const float*)d_in[4];
    const float* b_out = (const float*)d_in[5];
    float* out = (float*)d_out;

    sgemm_qkv_kernel<<<dim3(24, 32), 256>>>(x, W_qkv, b_qkv);
    attn_kernel<<<dim3(32, 32), 256>>>(mask);
    sgemm_out_kernel<<<dim3(8, 32), 256>>>(W_out, b_out, out);
}

// round 3
// speedup vs baseline: 1.2953x; 1.2953x over previous
#include <cuda_runtime.h>
#include <cuda_bf16.h>
#include <cstdint>

// Problem constants
#define B_  2
#define L_  2048
#define D_  1024
#define H_  16
#define DK_ 64
#define SCALE_ 0.125f   // 1/sqrt(64)

// f32 scratch
__device__ float g_q [B_*H_*L_*DK_];   // [b,h,l,dk]
__device__ float g_kT[B_*H_*DK_*L_];   // [b,h,dk,l]
__device__ float g_v [B_*H_*L_*DK_];   // [b,h,l,dk]
__device__ float g_o [B_*L_*D_];       // [b,l,h*64+dk]

// split-bf16 scratch (u32 = packed bf16x2 along k-pairs)
__device__ uint32_t g_xh [4096*512], g_xl [4096*512];   // X   [M][K/2]
__device__ uint32_t g_wqh[512*3072], g_wql[512*3072];   // Wqkv[K/2][N]
__device__ uint32_t g_oh [4096*512], g_ol [4096*512];   // O   [M][K/2]
__device__ uint32_t g_woh[512*1024], g_wol[512*1024];   // Wout[K/2][N]

// ---------------------------------------------------------------------------
// Split conversion kernels
// ---------------------------------------------------------------------------
__global__ void split_A(const float* __restrict__ in,
                        uint32_t* __restrict__ h, uint32_t* __restrict__ l, int n)
{
    int i = blockIdx.x * blockDim.x + threadIdx.x;
    if (i >= n) return;
    float2 a = ((const float2*)in)[i];
    __nv_bfloat162 hv;
    hv.x = __float2bfloat16_rn(a.x);
    hv.y = __float2bfloat16_rn(a.y);
    float rx = a.x - __bfloat162float(hv.x);
    float ry = a.y - __bfloat162float(hv.y);
    __nv_bfloat162 lv;
    lv.x = __float2bfloat16_rn(rx);
    lv.y = __float2bfloat16_rn(ry);
    h[i] = *reinterpret_cast<uint32_t*>(&hv);
    l[i] = *reinterpret_cast<uint32_t*>(&lv);
}

// B: [K][N] f32 -> [K/2][N] u32 (pair of consecutive k rows packed)
__global__ void split_B(const float* __restrict__ in,
                        uint32_t* __restrict__ h, uint32_t* __restrict__ l, int N)
{
    int n  = blockIdx.x * blockDim.x + threadIdx.x;
    int k2 = blockIdx.y;
    float a0 = in[(size_t)(2*k2)   * N + n];
    float a1 = in[(size_t)(2*k2+1) * N + n];
    __nv_bfloat162 hv;
    hv.x = __float2bfloat16_rn(a0);
    hv.y = __float2bfloat16_rn(a1);
    float r0 = a0 - __bfloat162float(hv.x);
    float r1 = a1 - __bfloat162float(hv.y);
    __nv_bfloat162 lv;
    lv.x = __float2bfloat16_rn(r0);
    lv.y = __float2bfloat16_rn(r1);
    size_t o = (size_t)k2 * N + n;
    h[o] = *reinterpret_cast<uint32_t*>(&hv);
    l[o] = *reinterpret_cast<uint32_t*>(&lv);
}

// ---------------------------------------------------------------------------
// bf16x3 GEMM: C[M=4096][N] = A[M][1024] * B[1024][N]
// Block 128x128, K-tile 32 (16 k-pairs), 256 threads (8 warps, warp 64x32).
// EPI=0: QKV scatter epilogue.  EPI=1: plain write + bias.
// ---------------------------------------------------------------------------
#define OAH 0
#define OAL 2560
#define OBH 5120
#define OBL 7296
#define STG 9472
#define GEMM_SMEM (2*STG*4)   // 75776 bytes

__device__ __forceinline__ void cp16(uint32_t saddr, const void* gptr) {
    asm volatile("cp.async.cg.shared.global [%0], [%1], 16;\n" :: "r"(saddr), "l"(gptr));
}
__device__ __forceinline__ void cp_commit() {
    asm volatile("cp.async.commit_group;\n" ::: "memory");
}

__device__ __forceinline__ void mma16816(float* c, const uint32_t* a, const uint32_t* b) {
    asm volatile(
        "mma.sync.aligned.m16n8k16.row.col.f32.bf16.bf16.f32 "
        "{%0,%1,%2,%3}, {%4,%5,%6,%7}, {%8,%9}, {%0,%1,%2,%3};\n"
        : "+f"(c[0]), "+f"(c[1]), "+f"(c[2]), "+f"(c[3])
        : "r"(a[0]), "r"(a[1]), "r"(a[2]), "r"(a[3]), "r"(b[0]), "r"(b[1]));
}

template<int EPI>
__global__ void __launch_bounds__(256, 1)
gemm_bf16x3(const uint32_t* __restrict__ Ah, const uint32_t* __restrict__ Al,
            const uint32_t* __restrict__ Bh, const uint32_t* __restrict__ Bl,
            const float* __restrict__ bias, float* __restrict__ outp, int N)
{
    extern __shared__ uint32_t sm[];
    const int tid  = threadIdx.x;
    const int lane = tid & 31;
    const int wid  = tid >> 5;
    const int wm   = wid >> 2;      // 0..1
    const int wn   = wid & 3;       // 0..3
    const int m0   = blockIdx.y * 128;
    const int n0   = blockIdx.x * 128;
    const int KP2  = 512;           // K/2

    const uint32_t sbase = (uint32_t)__cvta_generic_to_shared(sm);

    float C[4][4][4];
#pragma unroll
    for (int mt = 0; mt < 4; mt++)
#pragma unroll
        for (int nt = 0; nt < 4; nt++)
#pragma unroll
            for (int e = 0; e < 4; e++) C[mt][nt][e] = 0.f;

    auto load_stage = [&](int s, int kp0) {
        uint32_t sa = sbase + (uint32_t)(s * STG) * 4;
#pragma unroll
        for (int j = tid; j < 512; j += 256) {
            int row = j >> 2, c4 = (j & 3) << 2;
            cp16(sa + (OAH + row*20 + c4)*4, Ah + (size_t)(m0+row)*KP2 + kp0 + c4);
            cp16(sa + (OAL + row*20 + c4)*4, Al + (size_t)(m0+row)*KP2 + kp0 + c4);
        }
#pragma unroll
        for (int j = tid; j < 512; j += 256) {
            int row = j >> 5, c4 = (j & 31) << 2;
            cp16(sa + (OBH + row*136 + c4)*4, Bh + (size_t)(kp0+row)*N + n0 + c4);
            cp16(sa + (OBL + row*136 + c4)*4, Bl + (size_t)(kp0+row)*N + n0 + c4);
        }
    };

    load_stage(0, 0);
    cp_commit();

    const int T = 32;
    for (int t = 0; t < T; t++) {
        if (t + 1 < T) { load_stage((t+1)&1, (t+1)*16); cp_commit(); }
        if (t + 1 < T) asm volatile("cp.async.wait_group 1;\n" ::: "memory");
        else           asm volatile("cp.async.wait_group 0;\n" ::: "memory");
        __syncthreads();

        const uint32_t* S = sm + (t & 1) * STG;
#pragma unroll
        for (int ss = 0; ss < 2; ss++) {
            const int c2 = ss*8 + (lane & 3);
            uint32_t ah[4][4], al[4][4];
#pragma unroll
            for (int mt = 0; mt < 4; mt++) {
                const int r0 = wm*64 + mt*16 + (lane >> 2);
                ah[mt][0] = S[OAH + r0*20 + c2];
                ah[mt][1] = S[OAH + (r0+8)*20 + c2];
                ah[mt][2] = S[OAH + r0*20 + c2 + 4];
                ah[mt][3] = S[OAH + (r0+8)*20 + c2 + 4];
                al[mt][0] = S[OAL + r0*20 + c2];
                al[mt][1] = S[OAL + (r0+8)*20 + c2];
                al[mt][2] = S[OAL + r0*20 + c2 + 4];
                al[mt][3] = S[OAL + (r0+8)*20 + c2 + 4];
            }
            uint32_t bh[4][2], bl[4][2];
            const int k2 = ss*8 + (lane & 3);
#pragma unroll
            for (int nt = 0; nt < 4; nt++) {
                const int col = wn*32 + nt*8 + (lane >> 2);
                bh[nt][0] = S[OBH + k2*136 + col];
                bh[nt][1] = S[OBH + (k2+4)*136 + col];
                bl[nt][0] = S[OBL + k2*136 + col];
                bl[nt][1] = S[OBL + (k2+4)*136 + col];
            }
#pragma unroll
            for (int mt = 0; mt < 4; mt++)
#pragma unroll
                for (int nt = 0; nt < 4; nt++) {
                    mma16816(C[mt][nt], ah[mt], bh[nt]);
                    mma16816(C[mt][nt], ah[mt], bl[nt]);
                    mma16816(C[mt][nt], al[mt], bh[nt]);
                }
        }
        __syncthreads();
    }

    // Epilogue
#pragma unroll
    for (int mt = 0; mt < 4; mt++) {
#pragma unroll
        for (int nt = 0; nt < 4; nt++) {
            const int r = m0 + wm*64 + mt*16 + (lane >> 2);
            const int c = n0 + wn*32 + nt*8 + (lane & 3)*2;
            const float b0 = bias[c], b1 = bias[c+1];
            const float v00 = C[mt][nt][0]+b0, v01 = C[mt][nt][1]+b1;
            const float v10 = C[mt][nt][2]+b0, v11 = C[mt][nt][3]+b1;
            if (EPI == 0) {
                const int part = c >> 10;
                const int d  = c & 1023;
                const int h  = d >> 6;
                const int dk = d & 63;
                const int bI = r >> 11;
                const int l  = r & 2047;
                if (part == 1) {
                    const size_t base = (size_t)(bI*16 + h)*64;
                    g_kT[(base + dk    )*2048 + l    ] = v00;
                    g_kT[(base + dk + 1)*2048 + l    ] = v01;
                    g_kT[(base + dk    )*2048 + l + 8] = v10;
                    g_kT[(base + dk + 1)*2048 + l + 8] = v11;
                } else {
                    float* dst = (part == 0) ? g_q : g_v;
                    const size_t rb = ((size_t)(bI*16 + h)*2048 + l)*64 + dk;
                    *(float2*)&dst[rb]          = make_float2(v00, v01);
                    *(float2*)&dst[rb + 8*64]   = make_float2(v10, v11);
                }
            } else {
                *(float2*)&outp[(size_t)r*N + c]       = make_float2(v00, v01);
                *(float2*)&outp[(size_t)(r+8)*N + c]   = make_float2(v10, v11);
            }
        }
    }
}

// ---------------------------------------------------------------------------
// Flash attention: 64q x 64k tiles, 256 threads, 4x4/thread, register-chunked.
// Pad stride 68 floats (272B = 16-multiple) so float4 smem accesses are aligned.
// masked score := 0.0 (participates in max & denom); masked P := 0 in numerator.
// ---------------------------------------------------------------------------
#define QKP_STRIDE 68
#define ATTN_SMEM ((2*64*QKP_STRIDE + 64*64)*4)   // 51200 bytes

__global__ void __launch_bounds__(256)
attn_kernel(const int* __restrict__ mask)
{
    extern __shared__ float smf[];
    float (*Qs)[QKP_STRIDE] = reinterpret_cast<float(*)[QKP_STRIDE]>(smf);
    float (*KP)[QKP_STRIDE] = reinterpret_cast<float(*)[QKP_STRIDE]>(smf + 64*QKP_STRIDE);
    float (*Vs)[64]         = reinterpret_cast<float(*)[64]>(smf + 2*64*QKP_STRIDE);

    const int tid = threadIdx.x;
    const int tx = tid & 15, ty = tid >> 4;
    const int bh = blockIdx.y;
    const int b  = bh >> 4;
    const int q0 = blockIdx.x * 64;

    const float* qbase  = g_q  + ((size_t)bh * 2048 + q0) * 64;
    const float* kTbase = g_kT + (size_t)bh * 64 * 2048;
    const float* vbase  = g_v  + (size_t)bh * 2048 * 64;
    const int*   mbase  = mask + ((size_t)b * 2048 + q0) * 2048;
    const int    h      = bh & 15;

    // Load Q tile
#pragma unroll
    for (int it = 0; it < 4; it++) {
        const int e = it * 256 + tid;
        const int row = e >> 4, c4 = (e & 15) * 4;
        *(float4*)&Qs[row][c4] = *(const float4*)(qbase + (size_t)row * 64 + c4);
    }

    float o[4][4];
#pragma unroll
    for (int i = 0; i < 4; i++)
#pragma unroll
        for (int j = 0; j < 4; j++) o[i][j] = 0.f;
    float m_i[4], l_i[4];
#pragma unroll
    for (int i = 0; i < 4; i++) { m_i[i] = -1e30f; l_i[i] = 0.f; }

    for (int k0 = 0; k0 < 2048; k0 += 64) {
        __syncthreads();
#pragma unroll
        for (int it = 0; it < 4; it++) {
            const int e = it * 256 + tid;
            const int row = e >> 4, c4 = (e & 15) * 4;
            *(float4*)&KP[row][c4] = *(const float4*)(kTbase + (size_t)row * 2048 + k0 + c4);
            *(float4*)&Vs[row][c4] = *(const float4*)(vbase + (size_t)(k0 + row) * 64 + c4);
        }
        __syncthreads();

        // S = Q @ K^T
        float s[4][4];
#pragma unroll
        for (int i = 0; i < 4; i++)
#pragma unroll
            for (int j = 0; j < 4; j++) s[i][j] = 0.f;

#pragma unroll
        for (int kk8 = 0; kk8 < 8; kk8++) {
            float q[4][8];
#pragma unroll
            for (int i = 0; i < 4; i++) {
                float4 t0 = *(const float4*)&Qs[ty*4+i][kk8*8];
                float4 t1 = *(const float4*)&Qs[ty*4+i][kk8*8+4];
                q[i][0]=t0.x; q[i][1]=t0.y; q[i][2]=t0.z; q[i][3]=t0.w;
                q[i][4]=t1.x; q[i][5]=t1.y; q[i][6]=t1.z; q[i][7]=t1.w;
            }
#pragma unroll
            for (int k = 0; k < 8; k++) {
                const float4 kv = *(const float4*)&KP[kk8*8+k][tx*4];
#pragma unroll
                for (int i = 0; i < 4; i++) {
                    s[i][0] += q[i][k] * kv.x;
                    s[i][1] += q[i][k] * kv.y;
                    s[i][2] += q[i][k] * kv.z;
                    s[i][3] += q[i][k] * kv.w;
                }
            }
        }
        __syncthreads();

        // Mask + online softmax; write P into KP
#pragma unroll
        for (int i = 0; i < 4; i++) {
            const int4 mv = *(const int4*)(mbase + (size_t)(ty*4+i)*2048 + k0 + tx*4);
            const float sv0 = mv.x ? s[i][0] * SCALE_ : 0.f;
            const float sv1 = mv.y ? s[i][1] * SCALE_ : 0.f;
            const float sv2 = mv.z ? s[i][2] * SCALE_ : 0.f;
            const float sv3 = mv.w ? s[i][3] * SCALE_ : 0.f;

            float rmax = fmaxf(fmaxf(sv0, sv1), fmaxf(sv2, sv3));
#pragma unroll
            for (int off = 8; off; off >>= 1)
                rmax = fmaxf(rmax, __shfl_xor_sync(0xffffffffu, rmax, off));

            const float mn  = fmaxf(m_i[i], rmax);
            const float fac = __expf(m_i[i] - mn);
            const float p0 = __expf(sv0 - mn);
            const float p1 = __expf(sv1 - mn);
            const float p2 = __expf(sv2 - mn);
            const float p3 = __expf(sv3 - mn);

            float rsum = p0 + p1 + p2 + p3;
#pragma unroll
            for (int off = 8; off; off >>= 1)
                rsum += __shfl_xor_sync(0xffffffffu, rsum, off);

            l_i[i] = l_i[i] * fac + rsum;
            m_i[i] = mn;
            o[i][0] *= fac; o[i][1] *= fac; o[i][2] *= fac; o[i][3] *= fac;

            float4 pv;
            pv.x = mv.x ? p0 : 0.f;
            pv.y = mv.y ? p1 : 0.f;
            pv.z = mv.z ? p2 : 0.f;
            pv.w = mv.w ? p3 : 0.f;
            *(float4*)&KP[ty*4+i][tx*4] = pv;
        }
        __syncthreads();

        // O += P @ V
#pragma unroll
        for (int kk8 = 0; kk8 < 8; kk8++) {
            float p[4][8];
#pragma unroll
            for (int i = 0; i < 4; i++) {
                float4 t0 = *(const float4*)&KP[ty*4+i][kk8*8];
                float4 t1 = *(const float4*)&KP[ty*4+i][kk8*8+4];
                p[i][0]=t0.x; p[i][1]=t0.y; p[i][2]=t0.z; p[i][3]=t0.w;
                p[i][4]=t1.x; p[i][5]=t1.y; p[i][6]=t1.z; p[i][7]=t1.w;
            }
#pragma unroll
            for (int k = 0; k < 8; k++) {
                const float4 vv = *(const float4*)&Vs[kk8*8+k][tx*4];
#pragma unroll
                for (int i = 0; i < 4; i++) {
                    o[i][0] += p[i][k] * vv.x;
                    o[i][1] += p[i][k] * vv.y;
                    o[i][2] += p[i][k] * vv.z;
                    o[i][3] += p[i][k] * vv.w;
                }
            }
        }
    }

#pragma unroll
    for (int i = 0; i < 4; i++) {
        const float inv = 1.0f / l_i[i];
        float4 ov = make_float4(o[i][0]*inv, o[i][1]*inv, o[i][2]*inv, o[i][3]*inv);
        *(float4*)(g_o + ((size_t)b*2048 + q0 + ty*4 + i)*1024 + h*64 + tx*4) = ov;
    }
}

// ---------------------------------------------------------------------------

extern "C" void kernel_launch(void* const* d_in, const int* in_sizes, int n_in,
                              void* d_out, int out_size)
{
    const float* x     = (const float*)d_in[0];
    const int*   mask  = (const int*)  d_in[1];
    const float* W_qkv = (const float*)d_in[2];
    const float* b_qkv = (const float*)d_in[3];
    const float* W_out = (const float*)d_in[4];
    const float* b_out = (const float*)d_in[5];
    float* out = (float*)d_out;

    cudaFuncSetAttribute(gemm_bf16x3<0>, cudaFuncAttributeMaxDynamicSharedMemorySize, GEMM_SMEM);
    cudaFuncSetAttribute(gemm_bf16x3<1>, cudaFuncAttributeMaxDynamicSharedMemorySize, GEMM_SMEM);
    cudaFuncSetAttribute(attn_kernel,    cudaFuncAttributeMaxDynamicSharedMemorySize, ATTN_SMEM);

    uint32_t *xh, *xl, *wqh, *wql, *oh, *ol, *woh, *wol;
    cudaGetSymbolAddress((void**)&xh,  g_xh);
    cudaGetSymbolAddress((void**)&xl,  g_xl);
    cudaGetSymbolAddress((void**)&wqh, g_wqh);
    cudaGetSymbolAddress((void**)&wql, g_wql);
    cudaGetSymbolAddress((void**)&oh,  g_oh);
    cudaGetSymbolAddress((void**)&ol,  g_ol);
    cudaGetSymbolAddress((void**)&woh, g_woh);
    cudaGetSymbolAddress((void**)&wol, g_wol);
    float* o_f32;
    cudaGetSymbolAddress((void**)&o_f32, g_o);

    // Split X and W_qkv
    split_A<<<(4096*512)/256, 256>>>(x, xh, xl, 4096*512);
    split_B<<<dim3(3072/256, 512), 256>>>(W_qkv, wqh, wql, 3072);

    // QKV projection (scatter epilogue into g_q / g_kT / g_v)
    gemm_bf16x3<0><<<dim3(24, 32), 256, GEMM_SMEM>>>(xh, xl, wqh, wql, b_qkv, nullptr, 3072);

    // Attention
    attn_kernel<<<dim3(32, 32), 256, ATTN_SMEM>>>(mask);

    // Split O and W_out
    split_A<<<(4096*512)/256, 256>>>(o_f32, oh, ol, 4096*512);
    split_B<<<dim3(1024/256, 512), 256>>>(W_out, woh, wol, 1024);

    // Output projection
    gemm_bf16x3<1><<<dim3(8, 32), 256, GEMM_SMEM>>>(oh, ol, woh, wol, b_out, out, 1024);
}

// round 4
// speedup vs baseline: 2.3749x; 1.8334x over previous
#include <cuda_runtime.h>
#include <cuda_bf16.h>
#include <cstdint>

// Problem constants
#define B_  2
#define L_  2048
#define D_  1024
#define H_  16
#define DK_ 64
#define SCALE_ 0.125f   // 1/sqrt(64)

// split-bf16 scratch (u32 = packed bf16x2)
__device__ uint32_t g_xh [4096*512], g_xl [4096*512];   // X   [M][K/2]
__device__ uint32_t g_wqh[512*3072], g_wql[512*3072];   // Wqkv[K/2][N]
__device__ uint32_t g_oh [4096*512], g_ol [4096*512];   // O   [M][K/2]  (written by attn)
__device__ uint32_t g_woh[512*1024], g_wol[512*1024];   // Wout[K/2][N]

// attention operands, packed bf16x2 hi/lo
__device__ uint32_t g_qh [32*2048*32], g_ql [32*2048*32]; // Q  [bh][l][dk2]
__device__ uint32_t g_kh [32*32*2048], g_kl [32*32*2048]; // K  [bh][dk2][l]
__device__ uint32_t g_vth[32*2048*32], g_vtl[32*2048*32]; // Vt [bh][l][dk2] (pre-repack)
__device__ uint32_t g_vh [32*1024*64], g_vl [32*1024*64]; // V  [bh][l2][dk] (pairs along l)
__device__ uint32_t g_mb [2*2048*64];                     // mask bits [b][q][64 words]

// ---------------------------------------------------------------------------
// Helpers
// ---------------------------------------------------------------------------
__device__ __forceinline__ uint32_t pack_hl(float a, float b, uint32_t& lo) {
    __nv_bfloat162 t, u;
    t.x = __float2bfloat16_rn(a);
    t.y = __float2bfloat16_rn(b);
    u.x = __float2bfloat16_rn(a - __bfloat162float(t.x));
    u.y = __float2bfloat16_rn(b - __bfloat162float(t.y));
    lo = *reinterpret_cast<uint32_t*>(&u);
    return *reinterpret_cast<uint32_t*>(&t);
}

__device__ __forceinline__ void cp16(uint32_t saddr, const void* gptr) {
    asm volatile("cp.async.cg.shared.global [%0], [%1], 16;\n" :: "r"(saddr), "l"(gptr));
}
__device__ __forceinline__ void cp_commit() {
    asm volatile("cp.async.commit_group;\n" ::: "memory");
}
__device__ __forceinline__ void mma16816(float* c, const uint32_t* a, const uint32_t* b) {
    asm volatile(
        "mma.sync.aligned.m16n8k16.row.col.f32.bf16.bf16.f32 "
        "{%0,%1,%2,%3}, {%4,%5,%6,%7}, {%8,%9}, {%0,%1,%2,%3};\n"
        : "+f"(c[0]), "+f"(c[1]), "+f"(c[2]), "+f"(c[3])
        : "r"(a[0]), "r"(a[1]), "r"(a[2]), "r"(a[3]), "r"(b[0]), "r"(b[1]));
}

// ---------------------------------------------------------------------------
// Split conversion kernels
// ---------------------------------------------------------------------------
__global__ void split_A(const float* __restrict__ in,
                        uint32_t* __restrict__ h, uint32_t* __restrict__ l, int n)
{
    int i = blockIdx.x * blockDim.x + threadIdx.x;
    if (i >= n) return;
    float2 a = ((const float2*)in)[i];
    uint32_t lo;
    uint32_t hi = pack_hl(a.x, a.y, lo);
    h[i] = hi; l[i] = lo;
}

__global__ void split_B(const float* __restrict__ in,
                        uint32_t* __restrict__ h, uint32_t* __restrict__ l, int N)
{
    int n  = blockIdx.x * blockDim.x + threadIdx.x;
    int k2 = blockIdx.y;
    float a0 = in[(size_t)(2*k2)   * N + n];
    float a1 = in[(size_t)(2*k2+1) * N + n];
    uint32_t lo;
    uint32_t hi = pack_hl(a0, a1, lo);
    size_t o = (size_t)k2 * N + n;
    h[o] = hi; l[o] = lo;
}

// mask bit-pack: g_mb[b][q][w], bit j of word w = (mask[b][q][32w+j] != 0)
__global__ void maskpack(const int* __restrict__ mask)
{
    int idx = blockIdx.x * 256 + threadIdx.x;       // 0 .. 2*2048*64-1
    int w   = idx & 63;
    int row = idx >> 6;                              // b*2048 + q
    const int4* p = (const int4*)(mask + (size_t)row * 2048 + w * 32);
    uint32_t bits = 0;
#pragma unroll
    for (int i = 0; i < 8; i++) {
        int4 v = p[i];
        bits |= (uint32_t)(v.x != 0) << (4*i)
             |  (uint32_t)(v.y != 0) << (4*i+1)
             |  (uint32_t)(v.z != 0) << (4*i+2)
             |  (uint32_t)(v.w != 0) << (4*i+3);
    }
    g_mb[idx] = bits;
}

// V repack: [bh][l][dk2] (pairs along dk) -> [bh][l2][dk] (pairs along l)
__global__ void vrepack()
{
    int idx = blockIdx.x * 256 + threadIdx.x;       // 0 .. 32*1024*64-1
    int d  = idx & 63;
    int l2 = (idx >> 6) & 1023;
    int bh = idx >> 16;
    const uint16_t* th = (const uint16_t*)g_vth;
    const uint16_t* tl = (const uint16_t*)g_vtl;
    size_t i0 = ((size_t)bh*2048 + 2*l2    ) * 64 + d;
    size_t i1 = ((size_t)bh*2048 + 2*l2 + 1) * 64 + d;
    g_vh[idx] = (uint32_t)th[i0] | ((uint32_t)th[i1] << 16);
    g_vl[idx] = (uint32_t)tl[i0] | ((uint32_t)tl[i1] << 16);
}

// ---------------------------------------------------------------------------
// bf16x3 GEMM: block 128x128, K-tile 32, 256 threads.
// EPI=0: QKV epilogue -> packed bf16 Q/K/Vt.  EPI=1: plain f32 write + bias.
// ---------------------------------------------------------------------------
#define OAH 0
#define OAL 2560
#define OBH 5120
#define OBL 7296
#define STG 9472
#define GEMM_SMEM (2*STG*4)

template<int EPI>
__global__ void __launch_bounds__(256, 1)
gemm_bf16x3(const uint32_t* __restrict__ Ah, const uint32_t* __restrict__ Al,
            const uint32_t* __restrict__ Bh, const uint32_t* __restrict__ Bl,
            const float* __restrict__ bias, float* __restrict__ outp, int N)
{
    extern __shared__ uint32_t sm[];
    const int tid  = threadIdx.x;
    const int lane = tid & 31;
    const int wid  = tid >> 5;
    const int wm   = wid >> 2;
    const int wn   = wid & 3;
    const int m0   = blockIdx.y * 128;
    const int n0   = blockIdx.x * 128;
    const int KP2  = 512;

    const uint32_t sbase = (uint32_t)__cvta_generic_to_shared(sm);

    float C[4][4][4];
#pragma unroll
    for (int mt = 0; mt < 4; mt++)
#pragma unroll
        for (int nt = 0; nt < 4; nt++)
#pragma unroll
            for (int e = 0; e < 4; e++) C[mt][nt][e] = 0.f;

    auto load_stage = [&](int s, int kp0) {
        uint32_t sa = sbase + (uint32_t)(s * STG) * 4;
#pragma unroll
        for (int j = tid; j < 512; j += 256) {
            int row = j >> 2, c4 = (j & 3) << 2;
            cp16(sa + (OAH + row*20 + c4)*4, Ah + (size_t)(m0+row)*KP2 + kp0 + c4);
            cp16(sa + (OAL + row*20 + c4)*4, Al + (size_t)(m0+row)*KP2 + kp0 + c4);
        }
#pragma unroll
        for (int j = tid; j < 512; j += 256) {
            int row = j >> 5, c4 = (j & 31) << 2;
            cp16(sa + (OBH + row*136 + c4)*4, Bh + (size_t)(kp0+row)*N + n0 + c4);
            cp16(sa + (OBL + row*136 + c4)*4, Bl + (size_t)(kp0+row)*N + n0 + c4);
        }
    };

    load_stage(0, 0);
    cp_commit();

    const int T = 32;
    for (int t = 0; t < T; t++) {
        if (t + 1 < T) { load_stage((t+1)&1, (t+1)*16); cp_commit(); }
        if (t + 1 < T) asm volatile("cp.async.wait_group 1;\n" ::: "memory");
        else           asm volatile("cp.async.wait_group 0;\n" ::: "memory");
        __syncthreads();

        const uint32_t* S = sm + (t & 1) * STG;
#pragma unroll
        for (int ss = 0; ss < 2; ss++) {
            const int c2 = ss*8 + (lane & 3);
            uint32_t ah[4][4], al[4][4];
#pragma unroll
            for (int mt = 0; mt < 4; mt++) {
                const int r0 = wm*64 + mt*16 + (lane >> 2);
                ah[mt][0] = S[OAH + r0*20 + c2];
                ah[mt][1] = S[OAH + (r0+8)*20 + c2];
                ah[mt][2] = S[OAH + r0*20 + c2 + 4];
                ah[mt][3] = S[OAH + (r0+8)*20 + c2 + 4];
                al[mt][0] = S[OAL + r0*20 + c2];
                al[mt][1] = S[OAL + (r0+8)*20 + c2];
                al[mt][2] = S[OAL + r0*20 + c2 + 4];
                al[mt][3] = S[OAL + (r0+8)*20 + c2 + 4];
            }
            uint32_t bh[4][2], bl[4][2];
            const int k2 = ss*8 + (lane & 3);
#pragma unroll
            for (int nt = 0; nt < 4; nt++) {
                const int col = wn*32 + nt*8 + (lane >> 2);
                bh[nt][0] = S[OBH + k2*136 + col];
                bh[nt][1] = S[OBH + (k2+4)*136 + col];
                bl[nt][0] = S[OBL + k2*136 + col];
                bl[nt][1] = S[OBL + (k2+4)*136 + col];
            }
#pragma unroll
            for (int mt = 0; mt < 4; mt++)
#pragma unroll
                for (int nt = 0; nt < 4; nt++) {
                    mma16816(C[mt][nt], ah[mt], bh[nt]);
                    mma16816(C[mt][nt], ah[mt], bl[nt]);
                    mma16816(C[mt][nt], al[mt], bh[nt]);
                }
        }
        __syncthreads();
    }

    // Epilogue
#pragma unroll
    for (int mt = 0; mt < 4; mt++) {
#pragma unroll
        for (int nt = 0; nt < 4; nt++) {
            const int r = m0 + wm*64 + mt*16 + (lane >> 2);
            const int c = n0 + wn*32 + nt*8 + (lane & 3)*2;
            const float b0 = bias[c], b1 = bias[c+1];
            const float v00 = C[mt][nt][0]+b0, v01 = C[mt][nt][1]+b1;
            const float v10 = C[mt][nt][2]+b0, v11 = C[mt][nt][3]+b1;
            if (EPI == 0) {
                const int part = c >> 10;
                const int d   = c & 1023;
                const int h   = d >> 6;
                const int dk2 = (d & 63) >> 1;
                const int bI  = r >> 11;
                const int l   = r & 2047;
                const int bh  = bI*16 + h;
                uint32_t lo0, lo1;
                uint32_t hi0 = pack_hl(v00, v01, lo0);
                uint32_t hi1 = pack_hl(v10, v11, lo1);
                if (part == 0) {
                    size_t i0 = ((size_t)bh*2048 + l)*32 + dk2;
                    g_qh[i0] = hi0;       g_ql[i0] = lo0;
                    g_qh[i0 + 8*32] = hi1; g_ql[i0 + 8*32] = lo1;
                } else if (part == 1) {
                    size_t i0 = ((size_t)bh*32 + dk2)*2048 + l;
                    g_kh[i0]     = hi0;  g_kl[i0]     = lo0;
                    g_kh[i0 + 8] = hi1;  g_kl[i0 + 8] = lo1;
                } else {
                    size_t i0 = ((size_t)bh*2048 + l)*32 + dk2;
                    g_vth[i0] = hi0;       g_vtl[i0] = lo0;
                    g_vth[i0 + 8*32] = hi1; g_vtl[i0 + 8*32] = lo1;
                }
            } else {
                *(float2*)&outp[(size_t)r*N + c]     = make_float2(v00, v01);
                *(float2*)&outp[(size_t)(r+8)*N + c] = make_float2(v10, v11);
            }
        }
    }
}

// ---------------------------------------------------------------------------
// Tensor-core flash attention. Block: 128 queries, 8 warps (16 rows each),
// key tiles of 64. bf16x3 S, P-split x V-split (3 MMAs) PV.
// ---------------------------------------------------------------------------
#define AKH 0
#define AKL 2304
#define AVH 4608
#define AVL 6912
#define ASTG 9216
#define ATTN_SMEM (2*ASTG*4)   // 73728 bytes

__device__ __forceinline__ void softmax_row(float (&sC)[8][4], float (&oC)[8][4],
                                            int e0, uint32_t w0, uint32_t w1,
                                            int c, float& mi, float& li)
{
    float rm = -1e30f;
    uint32_t rbits = 0;
#pragma unroll
    for (int j = 0; j < 8; j++) {
        const uint32_t w = (j < 4) ? w0 : w1;
#pragma unroll
        for (int e = 0; e < 2; e++) {
            const int col = 8*j + 2*c + e;
            const uint32_t bit = (w >> (col & 31)) & 1u;
            const float sv = bit ? sC[j][e0+e]*SCALE_ : 0.f;
            sC[j][e0+e] = sv;
            rbits |= bit << (2*j + e);
            rm = fmaxf(rm, sv);
        }
    }
    rm = fmaxf(rm, __shfl_xor_sync(0xffffffffu, rm, 1));
    rm = fmaxf(rm, __shfl_xor_sync(0xffffffffu, rm, 2));
    const float mn  = fmaxf(mi, rm);
    const float fac = __expf(mi - mn);
    float rs = 0.f;
#pragma unroll
    for (int j = 0; j < 8; j++)
#pragma unroll
        for (int e = 0; e < 2; e++) {
            const float pd = __expf(sC[j][e0+e] - mn);
            rs += pd;
            sC[j][e0+e] = ((rbits >> (2*j + e)) & 1u) ? pd : 0.f;
        }
    rs += __shfl_xor_sync(0xffffffffu, rs, 1);
    rs += __shfl_xor_sync(0xffffffffu, rs, 2);
    li = li*fac + rs;
    mi = mn;
#pragma unroll
    for (int j = 0; j < 8; j++) { oC[j][e0] *= fac; oC[j][e0+1] *= fac; }
}

__global__ void __launch_bounds__(256, 1)
attn_mma_kernel()
{
    extern __shared__ uint32_t sm[];
    const int tid  = threadIdx.x;
    const int lane = tid & 31;
    const int wid  = tid >> 5;
    const int c    = lane & 3;
    const int rq   = lane >> 2;
    const int bh   = blockIdx.y;
    const int b    = bh >> 4;
    const int h    = bh & 15;
    const int q0   = blockIdx.x * 128;
    const int r0   = q0 + wid*16 + rq;     // rows r0, r0+8

    const uint32_t sbase = (uint32_t)__cvta_generic_to_shared(sm);

    // Q fragments (persist in registers)
    uint32_t qh[4][4], ql[4][4];
    {
        const uint32_t* Qh = g_qh + (size_t)bh*2048*32;
        const uint32_t* Ql = g_ql + (size_t)bh*2048*32;
#pragma unroll
        for (int t = 0; t < 4; t++) {
            qh[t][0] = Qh[(size_t)r0*32     + 8*t + c];
            qh[t][1] = Qh[(size_t)(r0+8)*32 + 8*t + c];
            qh[t][2] = Qh[(size_t)r0*32     + 8*t + c + 4];
            qh[t][3] = Qh[(size_t)(r0+8)*32 + 8*t + c + 4];
            ql[t][0] = Ql[(size_t)r0*32     + 8*t + c];
            ql[t][1] = Ql[(size_t)(r0+8)*32 + 8*t + c];
            ql[t][2] = Ql[(size_t)r0*32     + 8*t + c + 4];
            ql[t][3] = Ql[(size_t)(r0+8)*32 + 8*t + c + 4];
        }
    }

    float oC[8][4];
#pragma unroll
    for (int j = 0; j < 8; j++)
#pragma unroll
        for (int e = 0; e < 4; e++) oC[j][e] = 0.f;
    float mi[2] = {-1e30f, -1e30f};
    float li[2] = {0.f, 0.f};

    auto load_stage = [&](int s, int k0) {
        const uint32_t sa = sbase + (uint32_t)(s * ASTG) * 4;
#pragma unroll
        for (int it = 0; it < 2; it++) {
            const int idx = it*256 + tid;
            const int row = idx >> 4;
            const int c4  = (idx & 15) * 4;
            cp16(sa + (AKH + row*72 + c4)*4, g_kh + ((size_t)bh*32 + row)*2048 + k0 + c4);
            cp16(sa + (AKL + row*72 + c4)*4, g_kl + ((size_t)bh*32 + row)*2048 + k0 + c4);
            cp16(sa + (AVH + row*72 + c4)*4, g_vh + ((size_t)bh*1024 + (k0>>1) + row)*64 + c4);
            cp16(sa + (AVL + row*72 + c4)*4, g_vl + ((size_t)bh*1024 + (k0>>1) + row)*64 + c4);
        }
    };

    load_stage(0, 0);
    cp_commit();

    const uint32_t* MB = g_mb + (size_t)b*2048*64;

    for (int t32 = 0; t32 < 32; t32++) {
        const int k0 = t32 * 64;
        if (t32 + 1 < 32) { load_stage((t32+1)&1, k0 + 64); cp_commit(); }
        if (t32 + 1 < 32) asm volatile("cp.async.wait_group 1;\n" ::: "memory");
        else              asm volatile("cp.async.wait_group 0;\n" ::: "memory");
        __syncthreads();

        const uint32_t* S = sm + (t32 & 1) * ASTG;

        // ---- S = Q @ K^T ----
        float sC[8][4];
#pragma unroll
        for (int j = 0; j < 8; j++)
#pragma unroll
            for (int e = 0; e < 4; e++) sC[j][e] = 0.f;

#pragma unroll
        for (int t = 0; t < 4; t++) {
#pragma unroll
            for (int j = 0; j < 8; j++) {
                uint32_t bhv[2], blv[2];
                bhv[0] = S[AKH + (8*t + c)*72     + 8*j + rq];
                bhv[1] = S[AKH + (8*t + c + 4)*72 + 8*j + rq];
                blv[0] = S[AKL + (8*t + c)*72     + 8*j + rq];
                blv[1] = S[AKL + (8*t + c + 4)*72 + 8*j + rq];
                mma16816(sC[j], qh[t], bhv);
                mma16816(sC[j], qh[t], blv);
                mma16816(sC[j], ql[t], bhv);
            }
        }

        // ---- masked online softmax ----
        const int wbase = k0 >> 5;
        const uint32_t w00 = MB[(size_t)r0*64 + wbase],     w01 = MB[(size_t)r0*64 + wbase + 1];
        const uint32_t w10 = MB[(size_t)(r0+8)*64 + wbase], w11 = MB[(size_t)(r0+8)*64 + wbase + 1];
        softmax_row(sC, oC, 0, w00, w01, c, mi[0], li[0]);
        softmax_row(sC, oC, 2, w10, w11, c, mi[1], li[1]);

        // ---- O += P @ V ----
#pragma unroll
        for (int tp = 0; tp < 4; tp++) {
            uint32_t pah[4], pal[4];
            pah[0] = pack_hl(sC[2*tp][0],   sC[2*tp][1],   pal[0]);
            pah[1] = pack_hl(sC[2*tp][2],   sC[2*tp][3],   pal[1]);
            pah[2] = pack_hl(sC[2*tp+1][0], sC[2*tp+1][1], pal[2]);
            pah[3] = pack_hl(sC[2*tp+1][2], sC[2*tp+1][3], pal[3]);
#pragma unroll
            for (int j = 0; j < 8; j++) {
                uint32_t bhv[2], blv[2];
                bhv[0] = S[AVH + (8*tp + c)*72     + 8*j + rq];
                bhv[1] = S[AVH + (8*tp + c + 4)*72 + 8*j + rq];
                blv[0] = S[AVL + (8*tp + c)*72     + 8*j + rq];
                blv[1] = S[AVL + (8*tp + c + 4)*72 + 8*j + rq];
                mma16816(oC[j], pah, bhv);
                mma16816(oC[j], pah, blv);
                mma16816(oC[j], pal, bhv);
            }
        }
        __syncthreads();
    }

    // ---- normalize + emit out-proj A operand (hi/lo split) ----
    const float inv0 = 1.0f / li[0];
    const float inv1 = 1.0f / li[1];
    const size_t mrow = (size_t)b*2048 + r0;
#pragma unroll
    for (int j = 0; j < 8; j++) {
        const int k2 = h*32 + 4*j + c;
        uint32_t lo0, lo1;
        uint32_t hi0 = pack_hl(oC[j][0]*inv0, oC[j][1]*inv0, lo0);
        uint32_t hi1 = pack_hl(oC[j][2]*inv1, oC[j][3]*inv1, lo1);
        g_oh[mrow*512 + k2]     = hi0;  g_ol[mrow*512 + k2]     = lo0;
        g_oh[(mrow+8)*512 + k2] = hi1;  g_ol[(mrow+8)*512 + k2] = lo1;
    }
}

// ---------------------------------------------------------------------------

extern "C" void kernel_launch(void* const* d_in, const int* in_sizes, int n_in,
                              void* d_out, int out_size)
{
    const float* x     = (const float*)d_in[0];
    const int*   mask  = (const int*)  d_in[1];
    const float* W_qkv = (const float*)d_in[2];
    const float* b_qkv = (const float*)d_in[3];
    const float* W_out = (const float*)d_in[4];
    const float* b_out = (const float*)d_in[5];
    float* out = (float*)d_out;

    cudaFuncSetAttribute(gemm_bf16x3<0>, cudaFuncAttributeMaxDynamicSharedMemorySize, GEMM_SMEM);
    cudaFuncSetAttribute(gemm_bf16x3<1>, cudaFuncAttributeMaxDynamicSharedMemorySize, GEMM_SMEM);
    cudaFuncSetAttribute(attn_mma_kernel, cudaFuncAttributeMaxDynamicSharedMemorySize, ATTN_SMEM);

    uint32_t *xh, *xl, *wqh, *wql, *oh, *ol, *woh, *wol;
    cudaGetSymbolAddress((void**)&xh,  g_xh);
    cudaGetSymbolAddress((void**)&xl,  g_xl);
    cudaGetSymbolAddress((void**)&wqh, g_wqh);
    cudaGetSymbolAddress((void**)&wql, g_wql);
    cudaGetSymbolAddress((void**)&oh,  g_oh);
    cudaGetSymbolAddress((void**)&ol,  g_ol);
    cudaGetSymbolAddress((void**)&woh, g_woh);
    cudaGetSymbolAddress((void**)&wol, g_wol);

    // Split X and W_qkv
    split_A<<<(4096*512)/256, 256>>>(x, xh, xl, 4096*512);
    split_B<<<dim3(3072/256, 512), 256>>>(W_qkv, wqh, wql, 3072);

    // Mask bit-pack (independent of QKV)
    maskpack<<<(2*2048*64)/256, 256>>>(mask);

    // QKV projection -> packed bf16 Q/K/Vt
    gemm_bf16x3<0><<<dim3(24, 32), 256, GEMM_SMEM>>>(xh, xl, wqh, wql, b_qkv, nullptr, 3072);

    // V repack (pairs along keys)
    vrepack<<<(32*1024*64)/256, 256>>>();

    // Tensor-core flash attention -> g_oh/g_ol
    attn_mma_kernel<<<dim3(16, 32), 256, ATTN_SMEM>>>();

    // Split W_out, output projection
    split_B<<<dim3(1024/256, 512), 256>>>(W_out, woh, wol, 1024);
    gemm_bf16x3<1><<<dim3(8, 32), 256, GEMM_SMEM>>>(oh, ol, woh, wol, b_out, out, 1024);
}